// round 9
// baseline (speedup 1.0000x reference)
#include <cuda_runtime.h>
#include <cuda_bf16.h>

#define N_SEQ   256
#define M_GENES 2000
#define D_DIM   128
#define N_NUC   4
#define ROWS_PER_WARP 8
#define TOTAL_ROWS (N_SEQ * M_GENES)       // 512000

// Single fused kernel, R2 write pattern:
//  warp -> 8 consecutive flat output rows (n*M + m), 4 KB contiguous write.
//  Normalization of each selected table row is recomputed in-warp
//  (shfl allreduce) -- redundant FLOPs are free under the write wall.
__global__ void __launch_bounds__(256) fused_kernel(
        const int* __restrict__ seq,
        const float* __restrict__ emb,
        float* __restrict__ out) {
    const unsigned int warp = (blockIdx.x * blockDim.x + threadIdx.x) >> 5;
    const unsigned int lane = threadIdx.x & 31u;
    const unsigned int row0 = warp * ROWS_PER_WARP;

    // 8 indices in one coalesced LDG (lanes 0..7)
    int g = 0;
    if (lane < ROWS_PER_WARP) g = __ldg(seq + row0 + lane);

    unsigned int m0 = row0 % M_GENES;      // may wrap the n boundary

    // ---- 8 independent table loads (MLP=8), straight from emb (L2-resident)
    float4 v[ROWS_PER_WARP];
    #pragma unroll
    for (int r = 0; r < ROWS_PER_WARP; r++) {
        int gr = __shfl_sync(0xffffffffu, g, r);
        unsigned int m = m0 + r;
        if (m >= M_GENES) m -= M_GENES;
        const float4* src = reinterpret_cast<const float4*>(
            emb + ((size_t)(m * N_NUC + gr)) * D_DIM);
        v[r] = __ldg(src + lane);
    }

    // ---- Per-row squared sums, then 8 interleaved warp allreduces
    float ss[ROWS_PER_WARP];
    #pragma unroll
    for (int r = 0; r < ROWS_PER_WARP; r++)
        ss[r] = v[r].x * v[r].x + v[r].y * v[r].y
              + v[r].z * v[r].z + v[r].w * v[r].w;

    #pragma unroll
    for (int o = 16; o > 0; o >>= 1) {
        #pragma unroll
        for (int r = 0; r < ROWS_PER_WARP; r++)
            ss[r] += __shfl_xor_sync(0xffffffffu, ss[r], o);
    }

    #pragma unroll
    for (int r = 0; r < ROWS_PER_WARP; r++) {
        float inv = 1.0f / fmaxf(sqrtf(ss[r]), 1e-12f);
        v[r].x *= inv; v[r].y *= inv; v[r].z *= inv; v[r].w *= inv;
    }

    // ---- 8 streaming stores: 4 KB contiguous per warp, sequential chip-wide
    float4* dst = reinterpret_cast<float4*>(out) + (size_t)row0 * 32 + lane;
    #pragma unroll
    for (int r = 0; r < ROWS_PER_WARP; r++)
        __stcs(dst + (size_t)r * 32, v[r]);
}

extern "C" void kernel_launch(void* const* d_in, const int* in_sizes, int n_in,
                              void* d_out, int out_size) {
    const int*   gene_seq = (const int*)d_in[0];     // (256, 2000) int32
    const float* emb      = (const float*)d_in[1];   // (2000, 4, 128) f32
    float*       out      = (float*)d_out;           // (256, 2000, 128) f32

    // 512000 rows / 8 per warp = 64000 warps; 8 warps per 256-thread block
    fused_kernel<<<TOTAL_ROWS / ROWS_PER_WARP / 8, 256>>>(gene_seq, emb, out);
}

// round 10
// speedup vs baseline: 1.3247x; 1.3247x over previous
#include <cuda_runtime.h>
#include <cuda_bf16.h>

#define N_SEQ   256
#define M_GENES 2000
#define D_DIM   128
#define N_NUC   4
#define TABLE_ROWS (M_GENES * N_NUC)       // 8000
#define ROWS_PER_WARP 8
#define TOTAL_ROWS (N_SEQ * M_GENES)       // 512000

// Tiny scratch: one inverse norm per table row (32 KB, no cudaMalloc allowed)
__device__ float g_inv_norm[TABLE_ROWS];

// Kernel 1: inverse norms only. One warp per 128-float row; writes 1 float.
__global__ void norms_kernel(const float* __restrict__ emb) {
    int warp = (blockIdx.x * blockDim.x + threadIdx.x) >> 5;
    int lane = threadIdx.x & 31;
    if (warp >= TABLE_ROWS) return;

    const float4* src = reinterpret_cast<const float4*>(emb + (size_t)warp * D_DIM);
    float4 v = __ldg(src + lane);
    float ss = v.x * v.x + v.y * v.y + v.z * v.z + v.w * v.w;
    #pragma unroll
    for (int o = 16; o > 0; o >>= 1)
        ss += __shfl_xor_sync(0xffffffffu, ss, o);

    if (lane == 0)
        g_inv_norm[warp] = 1.0f / fmaxf(sqrtf(ss), 1e-12f);
}

// Kernel 2: R2 gather structure. 8 consecutive output rows per warp (MLP=8),
// raw table row (L2-resident) * broadcast scalar inv-norm, contiguous stores.
__global__ void __launch_bounds__(256) gather_kernel(
        const int* __restrict__ seq,
        const float* __restrict__ emb,
        float* __restrict__ out) {
    const unsigned int warp = (blockIdx.x * blockDim.x + threadIdx.x) >> 5;
    const unsigned int lane = threadIdx.x & 31u;
    const unsigned int row0 = warp * ROWS_PER_WARP;

    // 8 indices in one coalesced LDG (lanes 0..7)
    int g = 0;
    if (lane < ROWS_PER_WARP) g = __ldg(seq + row0 + lane);

    unsigned int m0 = row0 % M_GENES;      // may wrap the n boundary

    // 8 independent row loads + 8 independent scalar inv-norm loads
    float4 v[ROWS_PER_WARP];
    float  s[ROWS_PER_WARP];
    #pragma unroll
    for (int r = 0; r < ROWS_PER_WARP; r++) {
        int gr = __shfl_sync(0xffffffffu, g, r);
        unsigned int m = m0 + r;
        if (m >= M_GENES) m -= M_GENES;
        unsigned int trow = m * N_NUC + gr;
        const float4* src = reinterpret_cast<const float4*>(
            emb + (size_t)trow * D_DIM);
        v[r] = __ldg(src + lane);          // 512 B row, L2-resident
        s[r] = __ldg(g_inv_norm + trow);   // broadcast scalar, L2-hit
    }

    // Scale + 8 streaming stores (4 KB contiguous per warp)
    float4* dst = reinterpret_cast<float4*>(out) + (size_t)row0 * 32 + lane;
    #pragma unroll
    for (int r = 0; r < ROWS_PER_WARP; r++) {
        float4 o;
        o.x = v[r].x * s[r];
        o.y = v[r].y * s[r];
        o.z = v[r].z * s[r];
        o.w = v[r].w * s[r];
        __stcs(dst + (size_t)r * 32, o);
    }
}

extern "C" void kernel_launch(void* const* d_in, const int* in_sizes, int n_in,
                              void* d_out, int out_size) {
    const int*   gene_seq = (const int*)d_in[0];     // (256, 2000) int32
    const float* emb      = (const float*)d_in[1];   // (2000, 4, 128) f32
    float*       out      = (float*)d_out;           // (256, 2000, 128) f32

    // Kernel 1: 8000 warps, bandwidth-trivial (4 MB read, 32 KB write)
    norms_kernel<<<(TABLE_ROWS * 32 + 255) / 256, 256>>>(emb);

    // Kernel 2: 512000 rows / 8 per warp = 64000 warps
    gather_kernel<<<TOTAL_ROWS / ROWS_PER_WARP / 8, 256>>>(gene_seq, emb, out);
}

// round 11
// speedup vs baseline: 1.3316x; 1.0052x over previous
#include <cuda_runtime.h>
#include <cuda_bf16.h>

#define N_SEQ   256
#define M_GENES 2000
#define D_DIM   128
#define N_NUC   4
#define TABLE_ROWS (M_GENES * N_NUC)       // 8000
#define ROWS_PER_WARP 8
#define TOTAL_ROWS (N_SEQ * M_GENES)       // 512000

// Tiny scratch: one inverse norm per table row (32 KB)
__device__ float g_inv_norm[TABLE_ROWS];

// Kernel 1: inverse norms only. One warp per 128-float row; writes 1 float.
// Fires the PDL trigger immediately so the gather can begin its independent
// prologue while the norms are still being computed.
__global__ void norms_kernel(const float* __restrict__ emb) {
#if __CUDA_ARCH__ >= 900
    cudaTriggerProgrammaticLaunchCompletion();
#endif
    int warp = (blockIdx.x * blockDim.x + threadIdx.x) >> 5;
    int lane = threadIdx.x & 31;
    if (warp >= TABLE_ROWS) return;

    const float4* src = reinterpret_cast<const float4*>(emb + (size_t)warp * D_DIM);
    float4 v = __ldg(src + lane);
    float ss = v.x * v.x + v.y * v.y + v.z * v.z + v.w * v.w;
    #pragma unroll
    for (int o = 16; o > 0; o >>= 1)
        ss += __shfl_xor_sync(0xffffffffu, ss, o);

    if (lane == 0)
        g_inv_norm[warp] = 1.0f / fmaxf(sqrtf(ss), 1e-12f);
}

// Kernel 2: floor gather (R9 body). 8 consecutive output rows per warp,
// MLP=8 row loads, broadcast scalar scale, 4 KB contiguous streaming stores.
// The g_inv_norm reads sit AFTER cudaGridDependencySynchronize(); everything
// before it depends only on seq/emb and overlaps with norms_kernel.
__global__ void __launch_bounds__(256) gather_kernel(
        const int* __restrict__ seq,
        const float* __restrict__ emb,
        float* __restrict__ out) {
    const unsigned int warp = (blockIdx.x * blockDim.x + threadIdx.x) >> 5;
    const unsigned int lane = threadIdx.x & 31u;
    const unsigned int row0 = warp * ROWS_PER_WARP;

    // 8 indices in one coalesced LDG (lanes 0..7) — independent of norms
    int g = 0;
    if (lane < ROWS_PER_WARP) g = __ldg(seq + row0 + lane);

    unsigned int m0 = row0 % M_GENES;      // may wrap the n boundary

    // 8 independent raw-row loads (L2-resident) — independent of norms
    float4 v[ROWS_PER_WARP];
    unsigned int trow[ROWS_PER_WARP];
    #pragma unroll
    for (int r = 0; r < ROWS_PER_WARP; r++) {
        int gr = __shfl_sync(0xffffffffu, g, r);
        unsigned int m = m0 + r;
        if (m >= M_GENES) m -= M_GENES;
        trow[r] = m * N_NUC + gr;
        const float4* src = reinterpret_cast<const float4*>(
            emb + (size_t)trow[r] * D_DIM);
        v[r] = __ldg(src + lane);
    }

#if __CUDA_ARCH__ >= 900
    cudaGridDependencySynchronize();       // wait for norms_kernel completion
#endif

    // 8 broadcast scalar inv-norm loads (L2-hit)
    float s[ROWS_PER_WARP];
    #pragma unroll
    for (int r = 0; r < ROWS_PER_WARP; r++)
        s[r] = __ldg(g_inv_norm + trow[r]);

    // Scale + 8 streaming stores (4 KB contiguous per warp)
    float4* dst = reinterpret_cast<float4*>(out) + (size_t)row0 * 32 + lane;
    #pragma unroll
    for (int r = 0; r < ROWS_PER_WARP; r++) {
        float4 o;
        o.x = v[r].x * s[r];
        o.y = v[r].y * s[r];
        o.z = v[r].z * s[r];
        o.w = v[r].w * s[r];
        __stcs(dst + (size_t)r * 32, o);
    }
}

extern "C" void kernel_launch(void* const* d_in, const int* in_sizes, int n_in,
                              void* d_out, int out_size) {
    const int*   gene_seq = (const int*)d_in[0];     // (256, 2000) int32
    const float* emb      = (const float*)d_in[1];   // (2000, 4, 128) f32
    float*       out      = (float*)d_out;           // (256, 2000, 128) f32

    // Kernel 1: norms (1000 blocks, one wave)
    norms_kernel<<<(TABLE_ROWS * 32 + 255) / 256, 256>>>(emb);

    // Kernel 2: gather, launched with PDL so its prologue overlaps kernel 1
    cudaLaunchConfig_t cfg = {};
    cfg.gridDim  = dim3(TOTAL_ROWS / ROWS_PER_WARP / 8);   // 8000 blocks
    cfg.blockDim = dim3(256);
    cfg.dynamicSmemBytes = 0;
    cfg.stream = 0;                                        // legacy stream, same as <<<>>>

    cudaLaunchAttribute attr[1];
    attr[0].id = cudaLaunchAttributeProgrammaticStreamSerialization;
    attr[0].val.programmaticStreamSerializationAllowed = 1;
    cfg.attrs = attr;
    cfg.numAttrs = 1;

    cudaLaunchKernelEx(&cfg, gather_kernel, gene_seq, emb, (float*)d_out);
}